// round 1
// baseline (speedup 1.0000x reference)
#include <cuda_runtime.h>
#include <math.h>
#include <stdint.h>

#define HN    512
#define NST   64
#define LL    2048
#define LF    4096
#define BT    8
#define NTH   512

// ---------------- scratch (no allocations allowed) ----------------
__device__ float2 g_AT[HN * LL];        // at_roots (h, l)          8.4 MB
__device__ float2 g_KF[HN * LF];        // kernel spectrum, /4096  16.8 MB
__device__ float  g_UT[BT * HN * LL];   // u transposed (b,h,l)    33.5 MB
__device__ float  g_YT[BT * HN * LL];   // y transposed (b,h,l)    33.5 MB
__device__ float2 g_TW[LF / 2];         // W_4096^k, k<2048

// ---------------- complex helpers ----------------
__device__ __forceinline__ float2 cadd(float2 a, float2 b) { return make_float2(a.x + b.x, a.y + b.y); }
__device__ __forceinline__ float2 csub(float2 a, float2 b) { return make_float2(a.x - b.x, a.y - b.y); }
__device__ __forceinline__ float2 cmulf(float2 a, float2 b) {
    return make_float2(fmaf(a.x, b.x, -(a.y * b.y)), fmaf(a.x, b.y, a.y * b.x));
}

// ---------------- twiddle table ----------------
__global__ void k_twiddle() {
    int k = blockIdx.x * blockDim.x + threadIdx.x;
    if (k < LF / 2) {
        double s, c;
        sincospi(-2.0 * (double)k / (double)LF, &s, &c);  // exp(-2*pi*i*k/4096)
        g_TW[k] = make_float2((float)c, (float)s);
    }
}

// ---------------- K1: Cauchy / at_roots ----------------
__global__ void k_cauchy(const float* __restrict__ Lre, const float* __restrict__ Lim,
                         const float* __restrict__ P, const float* __restrict__ B,
                         const float* __restrict__ C, const float* __restrict__ logstep) {
    __shared__ float2 s_lam[NST];
    __shared__ float4 s_wA[NST];   // (w00r,w00i,w01r,w01i)
    __shared__ float4 s_wB[NST];   // (w10r,w10i,w11r,w11i)
    int h = blockIdx.y;
    int t = threadIdx.x;
    if (t < NST) {
        int idx = h * NST + t;
        float lr = fminf(Lre[idx], -1e-4f);
        float li = Lim[idx];
        s_lam[t] = make_float2(lr, li);
        float pr = P[idx * 2], pi = P[idx * 2 + 1];
        float br = B[idx * 2], bi = B[idx * 2 + 1];
        float cr = C[idx * 2], ci = C[idx * 2 + 1];
        // a0 = conj(C), a1 = conj(P); b0 = B, b1 = P
        s_wA[t] = make_float4(cr * br + ci * bi, cr * bi - ci * br,
                              cr * pr + ci * pi, cr * pi - ci * pr);
        s_wB[t] = make_float4(pr * br + pi * bi, pr * bi - pi * br,
                              pr * pr + pi * pi, 0.0f);
    }
    __syncthreads();

    int l = blockIdx.x * blockDim.x + t;
    float ts = 2.0f * expf(-logstep[h]);                 // 2/step
    float theta = (float)l * (-2.0f * 3.14159265358979323846f / (float)LL);
    float sn, cs;
    sincosf(theta, &sn, &cs);                            // Omega = (cs, sn)
    float bpr = 1.0f + cs, bpi = sn;                     // 1 + Omega
    float amr = 1.0f - cs, ami = -sn;                    // 1 - Omega
    float invb = 1.0f / (bpr * bpr + bpi * bpi);
    float gr = ts * (amr * bpr + ami * bpi) * invb;
    float gi = ts * (ami * bpr - amr * bpi) * invb;
    float csr = 2.0f * bpr * invb;                       // c_scale = 2*conj(1+Omega)/|1+Omega|^2
    float csi = -2.0f * bpi * invb;

    float k00r = 0.f, k00i = 0.f, k01r = 0.f, k01i = 0.f;
    float k10r = 0.f, k10i = 0.f, k11r = 0.f, k11i = 0.f;
#pragma unroll 8
    for (int n = 0; n < NST; n++) {
        float2 lam = s_lam[n];
        float dr = gr - lam.x, di = gi - lam.y;
        float inv = __fdividef(1.0f, fmaf(dr, dr, di * di));
        float rr = dr * inv, ri = -di * inv;
        float4 wA = s_wA[n];
        float4 wB = s_wB[n];
        k00r = fmaf(wA.x, rr, fmaf(-wA.y, ri, k00r));
        k00i = fmaf(wA.x, ri, fmaf( wA.y, rr, k00i));
        k01r = fmaf(wA.z, rr, fmaf(-wA.w, ri, k01r));
        k01i = fmaf(wA.z, ri, fmaf( wA.w, rr, k01i));
        k10r = fmaf(wB.x, rr, fmaf(-wB.y, ri, k10r));
        k10i = fmaf(wB.x, ri, fmaf( wB.y, rr, k10i));
        k11r = fmaf(wB.z, rr, fmaf(-wB.w, ri, k11r));
        k11i = fmaf(wB.z, ri, fmaf( wB.w, rr, k11i));
    }
    float denr = 1.0f + k11r, deni = k11i;
    float invd = 1.0f / (denr * denr + deni * deni);
    float qr = k01r * k10r - k01i * k10i;
    float qi = k01r * k10i + k01i * k10r;
    float fr = (qr * denr + qi * deni) * invd;
    float fi = (qi * denr - qr * deni) * invd;
    float ar_ = k00r - fr, ai_ = k00i - fi;
    g_AT[h * LL + l] = make_float2(csr * ar_ - csi * ai_, csr * ai_ + csi * ar_);
}

// ---------------- shared-memory Stockham FFT ----------------
// NQ in {2048, 4096}; DIR=-1 forward, +1 inverse (unscaled). tw: 2048 W_4096 in smem.
// Result ends in the buffer passed as x (6 stages for both sizes). Caller syncs before call.
template <int NQ, int DIR>
__device__ void fft_smem(float2* x, float2* y, const float2* __restrict__ tw, int tid) {
    const int MULT = LF / NQ;
    const int QUART = NQ / 4;
    int n = NQ, s = 1, ls = 0;
    if (NQ == 2048) {  // one radix-2 stage so remaining length is a power of 4
        const int half = NQ / 2;
        for (int i = tid; i < half; i += NTH) {
            float2 x0 = x[i], x1 = x[i + half];
            float2 su = cadd(x0, x1), df = csub(x0, x1);
            float2 w = tw[i * MULT];
            if (DIR > 0) w.y = -w.y;
            y[2 * i] = su;
            y[2 * i + 1] = cmulf(df, w);
        }
        __syncthreads();
        float2* tt = x; x = y; y = tt;
        n >>= 1; s <<= 1; ls = 1;
    }
    while (n > 1) {
        for (int i = tid; i < QUART; i += NTH) {
            int q = i & (s - 1);
            int p = i >> ls;
            int rb = q + (p << ls);
            float2 x0 = x[rb];
            float2 x1 = x[rb + QUART];
            float2 x2 = x[rb + 2 * QUART];
            float2 x3 = x[rb + 3 * QUART];
            float2 a = cadd(x0, x2), b = csub(x0, x2);
            float2 c = cadd(x1, x3), d = csub(x1, x3);
            float2 t0 = cadd(a, c), t2 = csub(a, c);
            float2 id = (DIR < 0) ? make_float2(d.y, -d.x) : make_float2(-d.y, d.x);
            float2 t1 = cadd(b, id), t3 = csub(b, id);
            float2 w1 = tw[(p << ls) * MULT];
            if (DIR > 0) w1.y = -w1.y;
            float2 w2 = cmulf(w1, w1);
            float2 w3 = cmulf(w1, w2);
            int wb = q + (p << (ls + 2));
            y[wb] = t0;
            y[wb + s] = cmulf(t1, w1);
            y[wb + 2 * s] = cmulf(t2, w2);
            y[wb + 3 * s] = cmulf(t3, w3);
        }
        __syncthreads();
        float2* tt = x; x = y; y = tt;
        n >>= 2; s <<= 2; ls += 2;
    }
}

#define SMEM_FFT ((4096 + 4096 + 2048) * sizeof(float2))  // 80 KB

// ---------------- K2: per-h  K = ifft2048(at).real ; KF = fft4096(pad(K))/4096 ----------------
__global__ void k_kernelfft() {
    extern __shared__ float2 sm[];
    float2* buf0 = sm;
    float2* buf1 = sm + 4096;
    float2* stw  = sm + 8192;
    int h = blockIdx.x, t = threadIdx.x;
    for (int i = t; i < 2048; i += NTH) stw[i] = g_TW[i];
    for (int i = t; i < 2048; i += NTH) buf0[i] = g_AT[h * LL + i];
    __syncthreads();
    fft_smem<2048, +1>(buf0, buf1, stw, t);
    float kr[4];
#pragma unroll
    for (int j = 0; j < 4; j++) kr[j] = buf0[t + NTH * j].x * (1.0f / 2048.0f);
    __syncthreads();
#pragma unroll
    for (int j = 0; j < 4; j++) {
        buf0[t + NTH * j] = make_float2(kr[j], 0.0f);
        buf0[t + NTH * j + 2048] = make_float2(0.0f, 0.0f);
    }
    __syncthreads();
    fft_smem<4096, -1>(buf0, buf1, stw, t);
    const float sc = 1.0f / 4096.0f;
    for (int i = t; i < 4096; i += NTH) {
        float2 v = buf0[i];
        g_KF[h * LF + i] = make_float2(v.x * sc, v.y * sc);
    }
}

// ---------------- K3: transpose u (b,l,h) -> (b,h,l) ----------------
__global__ void k_transpose_in(const float* __restrict__ u) {
    __shared__ float tile[32][33];
    int b = blockIdx.z;
    int h0 = blockIdx.x * 32, l0 = blockIdx.y * 32;
    int tx = threadIdx.x, ty = threadIdx.y;
    const float* up = u + (size_t)b * LL * HN;
#pragma unroll
    for (int j = 0; j < 32; j += 8)
        tile[ty + j][tx] = up[(size_t)(l0 + ty + j) * HN + h0 + tx];
    __syncthreads();
    float* o = g_UT + (size_t)b * HN * LL;
#pragma unroll
    for (int j = 0; j < 32; j += 8)
        o[(size_t)(h0 + ty + j) * LL + l0 + tx] = tile[tx][ty + j];
}

// ---------------- K4: packed conv  z=u_b0+i*u_b1 ; ifft(fft(z)*KF) = y0 + i*y1 ----------------
__global__ void k_conv(const float* __restrict__ D) {
    extern __shared__ float2 sm[];
    float2* buf0 = sm;
    float2* buf1 = sm + 4096;
    float2* stw  = sm + 8192;
    int blk = blockIdx.x;
    int h = blk & (HN - 1);
    int bp = blk >> 9;   // 0..3
    int t = threadIdx.x;
    const float* u0 = g_UT + ((size_t)(2 * bp) * HN + h) * LL;
    const float* u1 = g_UT + ((size_t)(2 * bp + 1) * HN + h) * LL;
    for (int i = t; i < 2048; i += NTH) stw[i] = g_TW[i];
    for (int i = t; i < 2048; i += NTH) {
        buf0[i] = make_float2(u0[i], u1[i]);
        buf0[i + 2048] = make_float2(0.0f, 0.0f);
    }
    __syncthreads();
    fft_smem<4096, -1>(buf0, buf1, stw, t);
    const float2* kf = g_KF + (size_t)h * LF;
    for (int i = t; i < 4096; i += NTH) buf0[i] = cmulf(buf0[i], kf[i]);
    __syncthreads();
    fft_smem<4096, +1>(buf0, buf1, stw, t);
    float dv = D[h];
    float* y0 = g_YT + ((size_t)(2 * bp) * HN + h) * LL;
    float* y1 = g_YT + ((size_t)(2 * bp + 1) * HN + h) * LL;
    for (int i = t; i < 2048; i += NTH) {
        float2 w = buf0[i];
        y0[i] = fmaf(dv, u0[i], w.x);
        y1[i] = fmaf(dv, u1[i], w.y);
    }
}

// ---------------- K5: transpose y (b,h,l) -> out (b,l,h) ----------------
__global__ void k_transpose_out(float* __restrict__ out) {
    __shared__ float tile[32][33];
    int b = blockIdx.z;
    int l0 = blockIdx.x * 32, h0 = blockIdx.y * 32;
    int tx = threadIdx.x, ty = threadIdx.y;
    const float* yp = g_YT + (size_t)b * HN * LL;
#pragma unroll
    for (int j = 0; j < 32; j += 8)
        tile[ty + j][tx] = yp[(size_t)(h0 + ty + j) * LL + l0 + tx];
    __syncthreads();
    float* op = out + (size_t)b * LL * HN;
#pragma unroll
    for (int j = 0; j < 32; j += 8)
        op[(size_t)(l0 + ty + j) * HN + h0 + tx] = tile[tx][ty + j];
}

// ---------------- launch ----------------
extern "C" void kernel_launch(void* const* d_in, const int* in_sizes, int n_in,
                              void* d_out, int out_size) {
    const float* u   = (const float*)d_in[0];
    const float* Lre = (const float*)d_in[1];
    const float* Lim = (const float*)d_in[2];
    const float* P   = (const float*)d_in[3];
    const float* B   = (const float*)d_in[4];
    const float* C   = (const float*)d_in[5];
    const float* D   = (const float*)d_in[6];
    const float* lst = (const float*)d_in[7];

    cudaFuncSetAttribute(k_kernelfft, cudaFuncAttributeMaxDynamicSharedMemorySize, (int)SMEM_FFT);
    cudaFuncSetAttribute(k_conv,      cudaFuncAttributeMaxDynamicSharedMemorySize, (int)SMEM_FFT);

    k_twiddle<<<2, 1024>>>();
    k_cauchy<<<dim3(LL / 256, HN), 256>>>(Lre, Lim, P, B, C, lst);
    k_transpose_in<<<dim3(HN / 32, LL / 32, BT), dim3(32, 8)>>>(u);
    k_kernelfft<<<HN, NTH, SMEM_FFT>>>();
    k_conv<<<BT / 2 * HN, NTH, SMEM_FFT>>>(D);
    k_transpose_out<<<dim3(LL / 32, HN / 32, BT), dim3(32, 8)>>>((float*)d_out);
}

// round 2
// speedup vs baseline: 1.2031x; 1.2031x over previous
#include <cuda_runtime.h>
#include <math.h>
#include <stdint.h>

#define HN    512
#define NST   64
#define LL    2048
#define LF    4096
#define BT    8
#define NT    256

// ---------------- scratch ----------------
__device__ float2 g_AT[HN * LL];        // at_roots (h, l)
__device__ float2 g_KF[HN * LF];        // kernel spectrum / 4096
__device__ float  g_UT[BT * HN * LL];   // u transposed (b,h,l)
__device__ float  g_YT[BT * HN * LL];   // y transposed (b,h,l)
__device__ float2 g_TW[LF / 2];         // W_4096^k, k<2048

// ---------------- helpers ----------------
__device__ __forceinline__ float2 cadd(float2 a, float2 b) { return make_float2(a.x + b.x, a.y + b.y); }
__device__ __forceinline__ float2 csub(float2 a, float2 b) { return make_float2(a.x - b.x, a.y - b.y); }
__device__ __forceinline__ float2 cmulf(float2 a, float2 b) {
    return make_float2(fmaf(a.x, b.x, -(a.y * b.y)), fmaf(a.x, b.y, a.y * b.x));
}

// bank-conflict-avoiding swizzle for FFT smem buffers (float2-unit index)
#define SW(u) ((u) ^ (((u) >> 3) & 15))

// f32x2 packed math
__device__ __forceinline__ unsigned long long pk2(float a, float b) {
    unsigned long long r; asm("mov.b64 %0, {%1, %2};" : "=l"(r) : "f"(a), "f"(b)); return r;
}
__device__ __forceinline__ void up2(unsigned long long v, float& a, float& b) {
    asm("mov.b64 {%0, %1}, %2;" : "=f"(a), "=f"(b) : "l"(v));
}
__device__ __forceinline__ unsigned long long f2fma(unsigned long long a, unsigned long long b, unsigned long long c) {
    unsigned long long d; asm("fma.rn.f32x2 %0, %1, %2, %3;" : "=l"(d) : "l"(a), "l"(b), "l"(c)); return d;
}
__device__ __forceinline__ unsigned long long f2add(unsigned long long a, unsigned long long b) {
    unsigned long long d; asm("add.rn.f32x2 %0, %1, %2;" : "=l"(d) : "l"(a), "l"(b)); return d;
}
__device__ __forceinline__ unsigned long long f2mul(unsigned long long a, unsigned long long b) {
    unsigned long long d; asm("mul.rn.f32x2 %0, %1, %2;" : "=l"(d) : "l"(a), "l"(b)); return d;
}
__device__ __forceinline__ float rcpa(float x) {
    float r; asm("rcp.approx.f32 %0, %1;" : "=f"(r) : "f"(x)); return r;
}
__device__ __forceinline__ float hsum(unsigned long long v) {
    float a, b; up2(v, a, b); return a + b;
}

// ---------------- twiddle table ----------------
__global__ void k_twiddle() {
    int k = blockIdx.x * blockDim.x + threadIdx.x;
    if (k < LF / 2) {
        double s, c;
        sincospi(-2.0 * (double)k / (double)LF, &s, &c);
        g_TW[k] = make_float2((float)c, (float)s);
    }
}

// ---------------- radix-8 butterfly (DIR<0 fwd, DIR>0 inv) ----------------
template <int DIR>
__device__ __forceinline__ void bfly8(const float2 v[8], float2 X[8]) {
    float2 s0 = cadd(v[0], v[4]), d0 = csub(v[0], v[4]);
    float2 s1 = cadd(v[2], v[6]), d1 = csub(v[2], v[6]);
    float2 E0 = cadd(s0, s1), E2 = csub(s0, s1);
    float2 id1 = (DIR < 0) ? make_float2(d1.y, -d1.x) : make_float2(-d1.y, d1.x);
    float2 E1 = cadd(d0, id1), E3 = csub(d0, id1);
    float2 t0 = cadd(v[1], v[5]), u0 = csub(v[1], v[5]);
    float2 t1 = cadd(v[3], v[7]), u1 = csub(v[3], v[7]);
    float2 O0 = cadd(t0, t1), O2 = csub(t0, t1);
    float2 iu1 = (DIR < 0) ? make_float2(u1.y, -u1.x) : make_float2(-u1.y, u1.x);
    float2 O1 = cadd(u0, iu1), O3 = csub(u0, iu1);
    const float c = 0.70710678118654752440f;
    float2 w1O1, w2O2, w3O3;
    if (DIR < 0) {
        w1O1 = make_float2(c * (O1.x + O1.y), c * (O1.y - O1.x));
        w2O2 = make_float2(O2.y, -O2.x);
        w3O3 = make_float2(c * (O3.y - O3.x), -c * (O3.x + O3.y));
    } else {
        w1O1 = make_float2(c * (O1.x - O1.y), c * (O1.x + O1.y));
        w2O2 = make_float2(-O2.y, O2.x);
        w3O3 = make_float2(-c * (O3.x + O3.y), c * (O3.x - O3.y));
    }
    X[0] = cadd(E0, O0);   X[4] = csub(E0, O0);
    X[1] = cadd(E1, w1O1); X[5] = csub(E1, w1O1);
    X[2] = cadd(E2, w2O2); X[6] = csub(E2, w2O2);
    X[3] = cadd(E3, w3O3); X[7] = csub(E3, w3O3);
}

// ---------------- in-place swizzled Stockham FFT, NT=256 threads ----------------
// N=4096: 4 radix-8 stages. N=2048: 3 radix-8 + 1 (twiddle-free) radix-4 stage.
// Caller must __syncthreads() before calling. Buffer valid for all on return.
template <int N, int DIR>
__device__ __forceinline__ void fft_ip(float2* x, const float2* __restrict__ tw, int t) {
    const int MULT = LF / N;
    const int B8 = N / 8;
    const int BPT = B8 / NT;            // 2 for N=4096, 1 for N=2048
    const int NS8 = (N == 4096) ? 4 : 3;
    int s = 1, ls = 0;
#pragma unroll
    for (int st = 0; st < NS8; st++) {
        float2 v[BPT ? BPT : 1][8];
#pragma unroll
        for (int b = 0; b < BPT; b++) {
            int i = t + b * NT;
#pragma unroll
            for (int m = 0; m < 8; m++) v[b][m] = x[SW(i + m * B8)];
        }
        __syncthreads();
#pragma unroll
        for (int b = 0; b < BPT; b++) {
            int i = t + b * NT;
            int q = i & (s - 1), p = i >> ls;
            float2 X[8];
            bfly8<DIR>(v[b], X);
            int pt = (p << ls) * MULT;
            float2 w1 = tw[pt], w2 = tw[2 * pt], w3 = tw[3 * pt];
            if (DIR > 0) { w1.y = -w1.y; w2.y = -w2.y; w3.y = -w3.y; }
            float2 w4 = cmulf(w2, w2), w5 = cmulf(w2, w3);
            float2 w6 = cmulf(w3, w3), w7 = cmulf(w3, w4);
            int wb = q + (p << (ls + 3));
            x[SW(wb)]         = X[0];
            x[SW(wb + s)]     = cmulf(X[1], w1);
            x[SW(wb + 2 * s)] = cmulf(X[2], w2);
            x[SW(wb + 3 * s)] = cmulf(X[3], w3);
            x[SW(wb + 4 * s)] = cmulf(X[4], w4);
            x[SW(wb + 5 * s)] = cmulf(X[5], w5);
            x[SW(wb + 6 * s)] = cmulf(X[6], w6);
            x[SW(wb + 7 * s)] = cmulf(X[7], w7);
        }
        __syncthreads();
        s <<= 3; ls += 3;
    }
    if (N == 2048) {
        // final radix-4, s=512, p==0 for all -> twiddle-free, addresses read==write per thread
        float2 v[2][4];
#pragma unroll
        for (int b = 0; b < 2; b++) {
            int i = t + b * NT;
#pragma unroll
            for (int m = 0; m < 4; m++) v[b][m] = x[SW(i + m * 512)];
        }
        __syncthreads();
#pragma unroll
        for (int b = 0; b < 2; b++) {
            int i = t + b * NT;
            float2 a = cadd(v[b][0], v[b][2]), bb = csub(v[b][0], v[b][2]);
            float2 c = cadd(v[b][1], v[b][3]), d = csub(v[b][1], v[b][3]);
            float2 id = (DIR < 0) ? make_float2(d.y, -d.x) : make_float2(-d.y, d.x);
            x[SW(i)]        = cadd(a, c);
            x[SW(i + 512)]  = cadd(bb, id);
            x[SW(i + 1024)] = csub(a, c);
            x[SW(i + 1536)] = csub(bb, id);
        }
        __syncthreads();
    }
}

// ---------------- K1: Cauchy / at_roots (packed f32x2 over state pairs) ----------------
__global__ void __launch_bounds__(NT) k_cauchy(
        const float* __restrict__ Lre, const float* __restrict__ Lim,
        const float* __restrict__ P, const float* __restrict__ B,
        const float* __restrict__ C, const float* __restrict__ logstep) {
    __shared__ float4 s_q0[32];  // {-lr0,-lr1,-li0,-li1}
    __shared__ float4 s_q1[32];  // {w00r0,w00r1,w00i0,w00i1}
    __shared__ float4 s_q2[32];  // {w01r0,w01r1,w01i0,w01i1}
    __shared__ float4 s_q3[32];  // {w10r0,w10r1,w10i0,w10i1}
    __shared__ float2 s_q4[32];  // {w11r0,w11r1}
    int h = blockIdx.y;
    int t = threadIdx.x;
    if (t < 32) {
        float lr[2], li[2], w00r[2], w00i[2], w01r[2], w01i[2], w10r[2], w10i[2], w11r[2];
#pragma unroll
        for (int k = 0; k < 2; k++) {
            int idx = h * NST + 2 * t + k;
            lr[k] = fminf(Lre[idx], -1e-4f);
            li[k] = Lim[idx];
            float pr = P[idx * 2], pi = P[idx * 2 + 1];
            float br = B[idx * 2], bi = B[idx * 2 + 1];
            float cr = C[idx * 2], ci = C[idx * 2 + 1];
            w00r[k] = cr * br + ci * bi;  w00i[k] = cr * bi - ci * br;
            w01r[k] = cr * pr + ci * pi;  w01i[k] = cr * pi - ci * pr;
            w10r[k] = pr * br + pi * bi;  w10i[k] = pr * bi - pi * br;
            w11r[k] = pr * pr + pi * pi;
        }
        s_q0[t] = make_float4(-lr[0], -lr[1], -li[0], -li[1]);
        s_q1[t] = make_float4(w00r[0], w00r[1], w00i[0], w00i[1]);
        s_q2[t] = make_float4(w01r[0], w01r[1], w01i[0], w01i[1]);
        s_q3[t] = make_float4(w10r[0], w10r[1], w10i[0], w10i[1]);
        s_q4[t] = make_float2(w11r[0], w11r[1]);
    }
    __syncthreads();

    int l = blockIdx.x * NT + t;
    float ts = 2.0f * expf(-logstep[h]);
    float theta = (float)l * (-2.0f * 3.14159265358979323846f / (float)LL);
    float sn, cs;
    sincosf(theta, &sn, &cs);
    float bpr = 1.0f + cs, bpi = sn;
    float amr = 1.0f - cs, ami = -sn;
    float invb = 1.0f / (bpr * bpr + bpi * bpi);
    float gr = ts * (amr * bpr + ami * bpi) * invb;
    float gi = ts * (ami * bpr - amr * bpi) * invb;
    float csr = 2.0f * bpr * invb;
    float csi = -2.0f * bpi * invb;

    unsigned long long gr2 = pk2(gr, gr), gi2 = pk2(gi, gi);
    unsigned long long S0 = 0, S1 = 0, S2 = 0, S3 = 0, S4 = 0, S5 = 0, S6 = 0;
    unsigned long long S7 = 0, S8 = 0, S9 = 0, S10 = 0, S11 = 0, S12 = 0, S13 = 0;
#pragma unroll 8
    for (int j = 0; j < 32; j++) {
        float4 q0 = s_q0[j];
        unsigned long long dr = f2add(gr2, pk2(q0.x, q0.y));
        unsigned long long di = f2add(gi2, pk2(q0.z, q0.w));
        unsigned long long mag = f2fma(dr, dr, f2mul(di, di));
        float m0, m1; up2(mag, m0, m1);
        unsigned long long inv = pk2(rcpa(m0), rcpa(m1));
        unsigned long long rr  = f2mul(dr, inv);
        unsigned long long nri = f2mul(di, inv);   // = -ri
        float4 q1 = s_q1[j];
        unsigned long long wr = pk2(q1.x, q1.y), wi = pk2(q1.z, q1.w);
        S0 = f2fma(wr, rr, S0);  S1 = f2fma(wi, nri, S1);
        S2 = f2fma(wi, rr, S2);  S3 = f2fma(wr, nri, S3);
        float4 q2 = s_q2[j];
        wr = pk2(q2.x, q2.y); wi = pk2(q2.z, q2.w);
        S4 = f2fma(wr, rr, S4);  S5 = f2fma(wi, nri, S5);
        S6 = f2fma(wi, rr, S6);  S7 = f2fma(wr, nri, S7);
        float4 q3 = s_q3[j];
        wr = pk2(q3.x, q3.y); wi = pk2(q3.z, q3.w);
        S8 = f2fma(wr, rr, S8);   S9 = f2fma(wi, nri, S9);
        S10 = f2fma(wi, rr, S10); S11 = f2fma(wr, nri, S11);
        float2 q4 = s_q4[j];
        wr = pk2(q4.x, q4.y);
        S12 = f2fma(wr, rr, S12); S13 = f2fma(wr, nri, S13);
    }
    float k00r = hsum(S0) + hsum(S1),  k00i = hsum(S2) - hsum(S3);
    float k01r = hsum(S4) + hsum(S5),  k01i = hsum(S6) - hsum(S7);
    float k10r = hsum(S8) + hsum(S9),  k10i = hsum(S10) - hsum(S11);
    float k11r = hsum(S12),            k11i = -hsum(S13);

    float denr = 1.0f + k11r, deni = k11i;
    float invd = 1.0f / (denr * denr + deni * deni);
    float qr = k01r * k10r - k01i * k10i;
    float qi = k01r * k10i + k01i * k10r;
    float fr = (qr * denr + qi * deni) * invd;
    float fi = (qi * denr - qr * deni) * invd;
    float ar_ = k00r - fr, ai_ = k00i - fi;
    g_AT[h * LL + l] = make_float2(csr * ar_ - csi * ai_, csr * ai_ + csi * ar_);
}

// ---------------- K2: kernel spectrum via even/odd split ----------------
// ats = symmetrized at_roots -> KF[2k] = ats[k]/4096
// K = ifft2048(ats) (real); KF[2k+1] = fft2048(K * W4096^n)[k]/4096
__global__ void __launch_bounds__(NT) k_kernelfft() {
    extern __shared__ float2 sm[];
    float2* buf = sm;          // 2048
    float2* stw = sm + 2048;   // 2048
    int h = blockIdx.x, t = threadIdx.x;
    for (int i = t; i < 2048; i += NT) stw[i] = g_TW[i];
    for (int i = t; i < 2048; i += NT) buf[SW(i)] = g_AT[h * LL + i];
    __syncthreads();
    float2 a[8], bm[8];
#pragma unroll
    for (int j = 0; j < 8; j++) {
        int l = t + j * NT;
        a[j] = buf[SW(l)];
        bm[j] = buf[SW((2048 - l) & 2047)];
    }
    __syncthreads();
    float2* kfh = g_KF + (size_t)h * LF;
    const float s4 = 1.0f / 4096.0f;
#pragma unroll
    for (int j = 0; j < 8; j++) {
        int l = t + j * NT;
        float2 ats = make_float2(0.5f * (a[j].x + bm[j].x), 0.5f * (a[j].y - bm[j].y));
        buf[SW(l)] = ats;
        kfh[2 * l] = make_float2(ats.x * s4, ats.y * s4);
    }
    __syncthreads();
    fft_ip<2048, +1>(buf, stw, t);
#pragma unroll
    for (int j = 0; j < 8; j++) {
        int l = t + j * NT;
        float kr = buf[SW(l)].x * (1.0f / 2048.0f);
        float2 w = stw[l];
        buf[SW(l)] = make_float2(kr * w.x, kr * w.y);
    }
    __syncthreads();
    fft_ip<2048, -1>(buf, stw, t);
#pragma unroll
    for (int j = 0; j < 8; j++) {
        int l = t + j * NT;
        float2 v = buf[SW(l)];
        kfh[2 * l + 1] = make_float2(v.x * s4, v.y * s4);
    }
}

// ---------------- K3: transpose u (b,l,h) -> (b,h,l) ----------------
__global__ void k_transpose_in(const float* __restrict__ u) {
    __shared__ float tile[32][33];
    int b = blockIdx.z;
    int h0 = blockIdx.x * 32, l0 = blockIdx.y * 32;
    int tx = threadIdx.x, ty = threadIdx.y;
    const float* up = u + (size_t)b * LL * HN;
#pragma unroll
    for (int j = 0; j < 32; j += 8)
        tile[ty + j][tx] = up[(size_t)(l0 + ty + j) * HN + h0 + tx];
    __syncthreads();
    float* o = g_UT + (size_t)b * HN * LL;
#pragma unroll
    for (int j = 0; j < 32; j += 8)
        o[(size_t)(h0 + ty + j) * LL + l0 + tx] = tile[tx][ty + j];
}

// ---------------- K4: packed conv ----------------
__global__ void __launch_bounds__(NT, 4) k_conv(const float* __restrict__ D) {
    extern __shared__ float2 sm[];
    float2* buf = sm;          // 4096
    float2* stw = sm + 4096;   // 2048
    int blk = blockIdx.x;
    int h = blk & (HN - 1);
    int bp = blk >> 9;
    int t = threadIdx.x;
    const float* u0 = g_UT + ((size_t)(2 * bp) * HN + h) * LL;
    const float* u1 = g_UT + ((size_t)(2 * bp + 1) * HN + h) * LL;
    for (int i = t; i < 2048; i += NT) stw[i] = g_TW[i];
    for (int i = t; i < 2048; i += NT) {
        buf[SW(i)] = make_float2(u0[i], u1[i]);
        buf[SW(i + 2048)] = make_float2(0.0f, 0.0f);
    }
    __syncthreads();
    fft_ip<4096, -1>(buf, stw, t);
    const float2* kf = g_KF + (size_t)h * LF;
    for (int i = t; i < 4096; i += NT) buf[SW(i)] = cmulf(buf[SW(i)], kf[i]);
    __syncthreads();
    fft_ip<4096, +1>(buf, stw, t);
    float dv = D[h];
    float* y0 = g_YT + ((size_t)(2 * bp) * HN + h) * LL;
    float* y1 = g_YT + ((size_t)(2 * bp + 1) * HN + h) * LL;
    for (int i = t; i < 2048; i += NT) {
        float2 w = buf[SW(i)];
        y0[i] = fmaf(dv, u0[i], w.x);
        y1[i] = fmaf(dv, u1[i], w.y);
    }
}

// ---------------- K5: transpose y (b,h,l) -> out (b,l,h) ----------------
__global__ void k_transpose_out(float* __restrict__ out) {
    __shared__ float tile[32][33];
    int b = blockIdx.z;
    int l0 = blockIdx.x * 32, h0 = blockIdx.y * 32;
    int tx = threadIdx.x, ty = threadIdx.y;
    const float* yp = g_YT + (size_t)b * HN * LL;
#pragma unroll
    for (int j = 0; j < 32; j += 8)
        tile[ty + j][tx] = yp[(size_t)(h0 + ty + j) * LL + l0 + tx];
    __syncthreads();
    float* op = out + (size_t)b * LL * HN;
#pragma unroll
    for (int j = 0; j < 32; j += 8)
        op[(size_t)(l0 + ty + j) * HN + h0 + tx] = tile[tx][ty + j];
}

// ---------------- launch ----------------
extern "C" void kernel_launch(void* const* d_in, const int* in_sizes, int n_in,
                              void* d_out, int out_size) {
    const float* u   = (const float*)d_in[0];
    const float* Lre = (const float*)d_in[1];
    const float* Lim = (const float*)d_in[2];
    const float* P   = (const float*)d_in[3];
    const float* B   = (const float*)d_in[4];
    const float* C   = (const float*)d_in[5];
    const float* D   = (const float*)d_in[6];
    const float* lst = (const float*)d_in[7];

    const int smem_kf = (2048 + 2048) * sizeof(float2);   // 32 KB
    const int smem_cv = (4096 + 2048) * sizeof(float2);   // 48 KB
    cudaFuncSetAttribute(k_kernelfft, cudaFuncAttributeMaxDynamicSharedMemorySize, smem_kf);
    cudaFuncSetAttribute(k_conv,      cudaFuncAttributeMaxDynamicSharedMemorySize, smem_cv);

    k_twiddle<<<2, 1024>>>();
    k_cauchy<<<dim3(LL / NT, HN), NT>>>(Lre, Lim, P, B, C, lst);
    k_transpose_in<<<dim3(HN / 32, LL / 32, BT), dim3(32, 8)>>>(u);
    k_kernelfft<<<HN, NT, smem_kf>>>();
    k_conv<<<(BT / 2) * HN, NT, smem_cv>>>(D);
    k_transpose_out<<<dim3(LL / 32, HN / 32, BT), dim3(32, 8)>>>((float*)d_out);
}